// round 1
// baseline (speedup 1.0000x reference)
#include <cuda_runtime.h>
#include <math.h>
#include <float.h>

#define BT 2048
#define DMODEL 1024
#define S0 2048
#define S1 1024
#define S2 512
#define STOT 3584

// ---- static device scratch (no allocation allowed) ----
__device__ float g_h[BT * DMODEL];        // gelu(q@rW1+b)   8 MB
__device__ float g_scores[BT * STOT];     // all levels      29 MB
__device__ float g_route[BT * 3];
__device__ int   g_dynk[BT];

__device__ __forceinline__ float gelu_erf(float x) {
    return 0.5f * x * (1.0f + erff(x * 0.70710678118654752f));
}

// ============================================================================
// GEMM NN: g_h = gelu(A[BT,D] @ B[D,D] + bias)
// 64x64 block tile, K-tile 16, 256 threads, 4x4 register tile.
// ============================================================================
__global__ void gemm_h_kernel(const float* __restrict__ A,
                              const float* __restrict__ B,
                              const float* __restrict__ bias) {
    __shared__ float As[16][68];   // transposed A tile, padded (16B-aligned rows)
    __shared__ float Bs[16][68];   // natural B tile, padded
    const int tid = threadIdx.x;
    const int tx = tid & 15, ty = tid >> 4;
    const int m0 = blockIdx.y * 64, n0 = blockIdx.x * 64;

    const int ar = tid >> 2;            // A tile row 0..63
    const int akb = (tid & 3) << 2;     // A tile k offset (float4)
    const int bk = tid >> 4;            // B tile k row 0..15
    const int bc = (tid & 15) << 2;     // B tile col (float4)

    float acc[4][4] = {};
    for (int k0 = 0; k0 < DMODEL; k0 += 16) {
        float4 av = *(const float4*)&A[(size_t)(m0 + ar) * DMODEL + k0 + akb];
        As[akb + 0][ar] = av.x; As[akb + 1][ar] = av.y;
        As[akb + 2][ar] = av.z; As[akb + 3][ar] = av.w;
        float4 bv = *(const float4*)&B[(size_t)(k0 + bk) * DMODEL + n0 + bc];
        *(float4*)&Bs[bk][bc] = bv;
        __syncthreads();
        #pragma unroll
        for (int kk = 0; kk < 16; kk++) {
            float4 a4 = *(const float4*)&As[kk][ty * 4];
            float4 b4 = *(const float4*)&Bs[kk][tx * 4];
            float a[4] = {a4.x, a4.y, a4.z, a4.w};
            float b[4] = {b4.x, b4.y, b4.z, b4.w};
            #pragma unroll
            for (int i = 0; i < 4; i++)
                #pragma unroll
                for (int j = 0; j < 4; j++)
                    acc[i][j] += a[i] * b[j];
        }
        __syncthreads();
    }
    #pragma unroll
    for (int i = 0; i < 4; i++) {
        int m = m0 + ty * 4 + i;
        #pragma unroll
        for (int j = 0; j < 4; j++) {
            int n = n0 + tx * 4 + j;
            g_h[(size_t)m * DMODEL + n] = gelu_erf(acc[i][j] + bias[n]);
        }
    }
}

// ============================================================================
// GEMM NT: g_scores[:, off+n] = (A[BT,D] @ Kb[S,D]^T) * scale + sal[n]
// ============================================================================
__global__ void gemm_scores_kernel(const float* __restrict__ A,
                                   const float* __restrict__ Kb,
                                   const float* __restrict__ sal,
                                   int col_off) {
    __shared__ float As[16][68];
    __shared__ float Bs[16][68];
    const int tid = threadIdx.x;
    const int tx = tid & 15, ty = tid >> 4;
    const int m0 = blockIdx.y * 64, n0 = blockIdx.x * 64;

    const int r = tid >> 2;
    const int kb = (tid & 3) << 2;

    float acc[4][4] = {};
    for (int k0 = 0; k0 < DMODEL; k0 += 16) {
        float4 av = *(const float4*)&A[(size_t)(m0 + r) * DMODEL + k0 + kb];
        As[kb + 0][r] = av.x; As[kb + 1][r] = av.y;
        As[kb + 2][r] = av.z; As[kb + 3][r] = av.w;
        float4 bv = *(const float4*)&Kb[(size_t)(n0 + r) * DMODEL + k0 + kb];
        Bs[kb + 0][r] = bv.x; Bs[kb + 1][r] = bv.y;
        Bs[kb + 2][r] = bv.z; Bs[kb + 3][r] = bv.w;
        __syncthreads();
        #pragma unroll
        for (int kk = 0; kk < 16; kk++) {
            float4 a4 = *(const float4*)&As[kk][ty * 4];
            float4 b4 = *(const float4*)&Bs[kk][tx * 4];
            float a[4] = {a4.x, a4.y, a4.z, a4.w};
            float b[4] = {b4.x, b4.y, b4.z, b4.w};
            #pragma unroll
            for (int i = 0; i < 4; i++)
                #pragma unroll
                for (int j = 0; j < 4; j++)
                    acc[i][j] += a[i] * b[j];
        }
        __syncthreads();
    }
    const float scale = 0.03125f;  // 1/sqrt(1024)
    #pragma unroll
    for (int i = 0; i < 4; i++) {
        int m = m0 + ty * 4 + i;
        #pragma unroll
        for (int j = 0; j < 4; j++) {
            int n = n0 + tx * 4 + j;
            g_scores[(size_t)m * STOT + col_off + n] = acc[i][j] * scale + sal[n];
        }
    }
}

// ============================================================================
// Per-row router softmax (from g_h) + dyn_k predictor (from q).
// 128 threads/block: warp0 = route, threads 32..95 = 64 predictor dots.
// ============================================================================
__global__ void route_pred_kernel(const float* __restrict__ q,
                                  const float* __restrict__ rW2,
                                  const float* __restrict__ rb2,
                                  const float* __restrict__ pW1,
                                  const float* __restrict__ pb1,
                                  const float* __restrict__ pW2,
                                  const float* __restrict__ pb2) {
    const int row = blockIdx.x;
    const int tid = threadIdx.x;
    __shared__ float s_pred[64];

    if (tid < 32) {
        const float* h = &g_h[(size_t)row * DMODEL];
        float a0 = 0.f, a1 = 0.f, a2 = 0.f;
        for (int d = tid; d < DMODEL; d += 32) {
            float hv = h[d];
            a0 += hv * rW2[d * 3 + 0];
            a1 += hv * rW2[d * 3 + 1];
            a2 += hv * rW2[d * 3 + 2];
        }
        #pragma unroll
        for (int o = 16; o; o >>= 1) {
            a0 += __shfl_xor_sync(0xffffffffu, a0, o);
            a1 += __shfl_xor_sync(0xffffffffu, a1, o);
            a2 += __shfl_xor_sync(0xffffffffu, a2, o);
        }
        if (tid == 0) {
            a0 += rb2[0]; a1 += rb2[1]; a2 += rb2[2];
            float m = fmaxf(a0, fmaxf(a1, a2));
            float e0 = expf(a0 - m), e1 = expf(a1 - m), e2 = expf(a2 - m);
            float inv = 1.0f / (e0 + e1 + e2);
            g_route[row * 3 + 0] = e0 * inv;
            g_route[row * 3 + 1] = e1 * inv;
            g_route[row * 3 + 2] = e2 * inv;
        }
    } else if (tid < 96) {
        const int j = tid - 32;
        const float* qr = &q[(size_t)row * DMODEL];
        float acc = 0.f;
        #pragma unroll 8
        for (int d = 0; d < DMODEL; d++)
            acc += qr[d] * pW1[d * 64 + j];
        s_pred[j] = gelu_erf(acc + pb1[j]) * pW2[j];
    }
    __syncthreads();
    if (tid == 0) {
        float s = 0.f;
        for (int j = 0; j < 64; j++) s += s_pred[j];
        s += pb2[0];
        float sig = 1.0f / (1.0f + expf(-s));
        int k = (int)floorf(sig * 64.0f);
        k = max(1, min(64, k));
        g_dynk[row] = k;
    }
}

// ============================================================================
// Per-row fused top-dyn_k + softmax + V gather + route-weighted accumulate.
// One 256-thread block per token; scores in smem; streaming argmax.
// ============================================================================
__global__ void topk_attend_kernel(const float* __restrict__ V0,
                                   const float* __restrict__ V1,
                                   const float* __restrict__ V2,
                                   float* __restrict__ out) {
    const int row = blockIdx.x;
    const int tid = threadIdx.x;
    __shared__ float s_sc[S0];
    __shared__ float s_wv[8];
    __shared__ int   s_wi[8];
    __shared__ float s_bv;
    __shared__ int   s_bi;

    const int dynk = g_dynk[row];
    const float* Vp[3] = {V0, V1, V2};
    const int Ss[3] = {S0, S1, S2};

    float t0 = 0.f, t1 = 0.f, t2 = 0.f, t3 = 0.f;
    int off = 0;
    for (int l = 0; l < 3; l++) {
        const int S = Ss[l];
        const float* V = Vp[l];
        for (int i = tid; i < S; i += 256)
            s_sc[i] = g_scores[(size_t)row * STOT + off + i];
        __syncthreads();

        float n0 = 0.f, n1 = 0.f, n2 = 0.f, n3 = 0.f, den = 0.f, m0 = 0.f;
        for (int k = 0; k < dynk; k++) {
            float bv = -FLT_MAX;
            int bi = 0;
            for (int i = tid; i < S; i += 256) {
                float v = s_sc[i];
                if (v > bv) { bv = v; bi = i; }
            }
            #pragma unroll
            for (int o = 16; o; o >>= 1) {
                float ov = __shfl_down_sync(0xffffffffu, bv, o);
                int   oi = __shfl_down_sync(0xffffffffu, bi, o);
                if (ov > bv) { bv = ov; bi = oi; }
            }
            if ((tid & 31) == 0) { s_wv[tid >> 5] = bv; s_wi[tid >> 5] = bi; }
            __syncthreads();
            if (tid == 0) {
                float b = s_wv[0]; int x = s_wi[0];
                #pragma unroll
                for (int w = 1; w < 8; w++)
                    if (s_wv[w] > b) { b = s_wv[w]; x = s_wi[w]; }
                s_bv = b; s_bi = x;
                s_sc[x] = -FLT_MAX;        // remove winner for next iteration
            }
            __syncthreads();
            const float val = s_bv;
            const int idx = s_bi;
            if (k == 0) m0 = val;
            const float w = expf(val - m0);
            den += w;
            const float* vr = V + (size_t)idx * DMODEL;
            n0 += w * vr[tid];
            n1 += w * vr[tid + 256];
            n2 += w * vr[tid + 512];
            n3 += w * vr[tid + 768];
        }
        const float rw = g_route[row * 3 + l] / den;
        t0 += rw * n0; t1 += rw * n1; t2 += rw * n2; t3 += rw * n3;
        off += S;
        __syncthreads();
    }
    out[(size_t)row * DMODEL + tid      ] = t0;
    out[(size_t)row * DMODEL + tid + 256] = t1;
    out[(size_t)row * DMODEL + tid + 512] = t2;
    out[(size_t)row * DMODEL + tid + 768] = t3;
}

// ============================================================================
extern "C" void kernel_launch(void* const* d_in, const int* in_sizes, int n_in,
                              void* d_out, int out_size) {
    const float* q    = (const float*)d_in[0];
    const float* K0   = (const float*)d_in[1];
    const float* V0   = (const float*)d_in[2];
    const float* sal0 = (const float*)d_in[3];
    const float* K1   = (const float*)d_in[4];
    const float* V1   = (const float*)d_in[5];
    const float* sal1 = (const float*)d_in[6];
    const float* K2   = (const float*)d_in[7];
    const float* V2   = (const float*)d_in[8];
    const float* sal2 = (const float*)d_in[9];
    const float* rW1  = (const float*)d_in[10];
    const float* rb1  = (const float*)d_in[11];
    const float* rW2  = (const float*)d_in[12];
    const float* rb2  = (const float*)d_in[13];
    const float* pW1  = (const float*)d_in[14];
    const float* pb1  = (const float*)d_in[15];
    const float* pW2  = (const float*)d_in[16];
    const float* pb2  = (const float*)d_in[17];
    float* out = (float*)d_out;

    // 1) hidden = gelu(q @ rW1 + rb1)
    gemm_h_kernel<<<dim3(DMODEL / 64, BT / 64), 256>>>(q, rW1, rb1);
    // 2) route softmax + dyn_k predictor
    route_pred_kernel<<<BT, 128>>>(q, rW2, rb2, pW1, pb1, pW2, pb2);
    // 3) scores per level
    gemm_scores_kernel<<<dim3(S0 / 64, BT / 64), 256>>>(q, K0, sal0, 0);
    gemm_scores_kernel<<<dim3(S1 / 64, BT / 64), 256>>>(q, K1, sal1, S0);
    gemm_scores_kernel<<<dim3(S2 / 64, BT / 64), 256>>>(q, K2, sal2, S0 + S1);
    // 4) fused top-k / softmax / gather / combine
    topk_attend_kernel<<<BT, 256>>>(V0, V1, V2, out);
}

// round 2
// speedup vs baseline: 1.1808x; 1.1808x over previous
#include <cuda_runtime.h>
#include <math.h>
#include <float.h>

#define BT 2048
#define DMODEL 1024
#define S0 2048
#define S1 1024
#define S2 512
#define STOT 3584

// ---- static device scratch (no allocation allowed) ----
__device__ float g_h[BT * DMODEL];        // gelu(q@rW1+b)   8 MB
__device__ float g_scores[BT * STOT];     // all levels      29 MB
__device__ float g_route[BT * 3];
__device__ int   g_dynk[BT];

__device__ __forceinline__ float gelu_erf(float x) {
    return 0.5f * x * (1.0f + erff(x * 0.70710678118654752f));
}

// ============================================================================
// 128x128x8 SGEMM, 256 threads, 8x8 microtile (split 4+4), register prefetch.
// A[M,1024] row-major. B supplied transposed-per-variant via loader below.
// ============================================================================
#define BK 8
#define LDP 132   // padded smem row stride (floats)

// ---------------- NN variant: g_h = gelu(q @ rW1 + rb1) ----------------
__global__ __launch_bounds__(256, 2)
void gemm_h_kernel(const float* __restrict__ A,
                   const float* __restrict__ B,
                   const float* __restrict__ bias) {
    __shared__ float As[BK * LDP];
    __shared__ float Bs[BK * LDP];
    const int tid = threadIdx.x;
    const int tx = tid & 15, ty = tid >> 4;
    const int m0 = blockIdx.y * 128, n0 = blockIdx.x * 128;

    // A loader: one float4 along K
    const int aRow = tid >> 1;
    const int aK   = (tid & 1) << 2;
    // B loader (NN): one float4 along N
    const int bK = tid >> 5;
    const int bN = (tid & 31) << 2;

    float acc[8][8] = {};
    float4 av = *(const float4*)&A[(size_t)(m0 + aRow) * DMODEL + aK];
    float4 bv = *(const float4*)&B[(size_t)bK * DMODEL + n0 + bN];

    for (int k0 = 0; k0 < DMODEL; k0 += BK) {
        As[(aK + 0) * LDP + aRow] = av.x;
        As[(aK + 1) * LDP + aRow] = av.y;
        As[(aK + 2) * LDP + aRow] = av.z;
        As[(aK + 3) * LDP + aRow] = av.w;
        *(float4*)&Bs[bK * LDP + bN] = bv;
        __syncthreads();
        if (k0 + BK < DMODEL) {
            av = *(const float4*)&A[(size_t)(m0 + aRow) * DMODEL + k0 + BK + aK];
            bv = *(const float4*)&B[(size_t)(k0 + BK + bK) * DMODEL + n0 + bN];
        }
        #pragma unroll
        for (int k = 0; k < BK; k++) {
            float4 a0 = *(const float4*)&As[k * LDP + ty * 4];
            float4 a1 = *(const float4*)&As[k * LDP + ty * 4 + 64];
            float4 b0 = *(const float4*)&Bs[k * LDP + tx * 4];
            float4 b1 = *(const float4*)&Bs[k * LDP + tx * 4 + 64];
            float a[8] = {a0.x, a0.y, a0.z, a0.w, a1.x, a1.y, a1.z, a1.w};
            float b[8] = {b0.x, b0.y, b0.z, b0.w, b1.x, b1.y, b1.z, b1.w};
            #pragma unroll
            for (int i = 0; i < 8; i++)
                #pragma unroll
                for (int j = 0; j < 8; j++)
                    acc[i][j] += a[i] * b[j];
        }
        __syncthreads();
    }
    #pragma unroll
    for (int i = 0; i < 8; i++) {
        int m = m0 + ((i < 4) ? (ty * 4 + i) : (ty * 4 + 64 + (i - 4)));
        #pragma unroll
        for (int j = 0; j < 8; j++) {
            int n = n0 + ((j < 4) ? (tx * 4 + j) : (tx * 4 + 64 + (j - 4)));
            g_h[(size_t)m * DMODEL + n] = gelu_erf(acc[i][j] + bias[n]);
        }
    }
}

// ---------------- NT variant: all three score levels in ONE launch ----------
// blockIdx.x tile -> level: [0,16)=L0, [16,24)=L1, [24,28)=L2
__global__ __launch_bounds__(256, 2)
void gemm_scores_kernel(const float* __restrict__ A,
                        const float* __restrict__ K0p,
                        const float* __restrict__ K1p,
                        const float* __restrict__ K2p,
                        const float* __restrict__ sal0,
                        const float* __restrict__ sal1,
                        const float* __restrict__ sal2) {
    __shared__ float As[BK * LDP];
    __shared__ float Bs[BK * LDP];
    const int tid = threadIdx.x;
    const int tx = tid & 15, ty = tid >> 4;
    const int m0 = blockIdx.y * 128;

    const int nt = blockIdx.x;
    const float* Kb; const float* sal; int n0, col_off;
    if (nt < 16)      { Kb = K0p; sal = sal0; n0 = nt * 128;        col_off = 0; }
    else if (nt < 24) { Kb = K1p; sal = sal1; n0 = (nt - 16) * 128; col_off = S0; }
    else              { Kb = K2p; sal = sal2; n0 = (nt - 24) * 128; col_off = S0 + S1; }

    const int aRow = tid >> 1;
    const int aK   = (tid & 1) << 2;

    float acc[8][8] = {};
    float4 av = *(const float4*)&A[(size_t)(m0 + aRow) * DMODEL + aK];
    float4 bv = *(const float4*)&Kb[(size_t)(n0 + aRow) * DMODEL + aK];

    for (int k0 = 0; k0 < DMODEL; k0 += BK) {
        As[(aK + 0) * LDP + aRow] = av.x;
        As[(aK + 1) * LDP + aRow] = av.y;
        As[(aK + 2) * LDP + aRow] = av.z;
        As[(aK + 3) * LDP + aRow] = av.w;
        Bs[(aK + 0) * LDP + aRow] = bv.x;
        Bs[(aK + 1) * LDP + aRow] = bv.y;
        Bs[(aK + 2) * LDP + aRow] = bv.z;
        Bs[(aK + 3) * LDP + aRow] = bv.w;
        __syncthreads();
        if (k0 + BK < DMODEL) {
            av = *(const float4*)&A[(size_t)(m0 + aRow) * DMODEL + k0 + BK + aK];
            bv = *(const float4*)&Kb[(size_t)(n0 + aRow) * DMODEL + k0 + BK + aK];
        }
        #pragma unroll
        for (int k = 0; k < BK; k++) {
            float4 a0 = *(const float4*)&As[k * LDP + ty * 4];
            float4 a1 = *(const float4*)&As[k * LDP + ty * 4 + 64];
            float4 b0 = *(const float4*)&Bs[k * LDP + tx * 4];
            float4 b1 = *(const float4*)&Bs[k * LDP + tx * 4 + 64];
            float a[8] = {a0.x, a0.y, a0.z, a0.w, a1.x, a1.y, a1.z, a1.w};
            float b[8] = {b0.x, b0.y, b0.z, b0.w, b1.x, b1.y, b1.z, b1.w};
            #pragma unroll
            for (int i = 0; i < 8; i++)
                #pragma unroll
                for (int j = 0; j < 8; j++)
                    acc[i][j] += a[i] * b[j];
        }
        __syncthreads();
    }
    const float scale = 0.03125f;  // 1/sqrt(1024)
    #pragma unroll
    for (int i = 0; i < 8; i++) {
        int m = m0 + ((i < 4) ? (ty * 4 + i) : (ty * 4 + 64 + (i - 4)));
        #pragma unroll
        for (int j = 0; j < 8; j++) {
            int nl = (j < 4) ? (tx * 4 + j) : (tx * 4 + 64 + (j - 4));
            int n = n0 + nl;
            g_scores[(size_t)m * STOT + col_off + n] = acc[i][j] * scale + sal[n];
        }
    }
}

// ============================================================================
// Per-row router softmax (from g_h) + dyn_k predictor (from q).
// ============================================================================
__global__ void route_pred_kernel(const float* __restrict__ q,
                                  const float* __restrict__ rW2,
                                  const float* __restrict__ rb2,
                                  const float* __restrict__ pW1,
                                  const float* __restrict__ pb1,
                                  const float* __restrict__ pW2,
                                  const float* __restrict__ pb2) {
    const int row = blockIdx.x;
    const int tid = threadIdx.x;
    __shared__ float s_pred[64];

    if (tid < 32) {
        const float* h = &g_h[(size_t)row * DMODEL];
        float a0 = 0.f, a1 = 0.f, a2 = 0.f;
        for (int d = tid; d < DMODEL; d += 32) {
            float hv = h[d];
            a0 += hv * rW2[d * 3 + 0];
            a1 += hv * rW2[d * 3 + 1];
            a2 += hv * rW2[d * 3 + 2];
        }
        #pragma unroll
        for (int o = 16; o; o >>= 1) {
            a0 += __shfl_xor_sync(0xffffffffu, a0, o);
            a1 += __shfl_xor_sync(0xffffffffu, a1, o);
            a2 += __shfl_xor_sync(0xffffffffu, a2, o);
        }
        if (tid == 0) {
            a0 += rb2[0]; a1 += rb2[1]; a2 += rb2[2];
            float m = fmaxf(a0, fmaxf(a1, a2));
            float e0 = expf(a0 - m), e1 = expf(a1 - m), e2 = expf(a2 - m);
            float inv = 1.0f / (e0 + e1 + e2);
            g_route[row * 3 + 0] = e0 * inv;
            g_route[row * 3 + 1] = e1 * inv;
            g_route[row * 3 + 2] = e2 * inv;
        }
    } else if (tid < 96) {
        const int j = tid - 32;
        const float* qr = &q[(size_t)row * DMODEL];
        float acc = 0.f;
        #pragma unroll 8
        for (int d = 0; d < DMODEL; d++)
            acc += qr[d] * pW1[d * 64 + j];
        s_pred[j] = gelu_erf(acc + pb1[j]) * pW2[j];
    }
    __syncthreads();
    if (tid == 0) {
        float s = 0.f;
        for (int j = 0; j < 64; j++) s += s_pred[j];
        s += pb2[0];
        float sig = 1.0f / (1.0f + expf(-s));
        int k = (int)floorf(sig * 64.0f);
        k = max(1, min(64, k));
        g_dynk[row] = k;
    }
}

// ============================================================================
// Per-row fused top-dyn_k + softmax + V gather + route-weighted accumulate.
// ============================================================================
__global__ void topk_attend_kernel(const float* __restrict__ V0,
                                   const float* __restrict__ V1,
                                   const float* __restrict__ V2,
                                   float* __restrict__ out) {
    const int row = blockIdx.x;
    const int tid = threadIdx.x;
    __shared__ float s_sc[S0];
    __shared__ float s_wv[8];
    __shared__ int   s_wi[8];
    __shared__ float s_bv;
    __shared__ int   s_bi;

    const int dynk = g_dynk[row];
    const float* Vp[3] = {V0, V1, V2};
    const int Ss[3] = {S0, S1, S2};

    float t0 = 0.f, t1 = 0.f, t2 = 0.f, t3 = 0.f;
    int off = 0;
    for (int l = 0; l < 3; l++) {
        const int S = Ss[l];
        const float* V = Vp[l];
        for (int i = tid; i < S; i += 256)
            s_sc[i] = g_scores[(size_t)row * STOT + off + i];
        __syncthreads();

        float n0 = 0.f, n1 = 0.f, n2 = 0.f, n3 = 0.f, den = 0.f, m0 = 0.f;
        for (int k = 0; k < dynk; k++) {
            float bv = -FLT_MAX;
            int bi = 0;
            for (int i = tid; i < S; i += 256) {
                float v = s_sc[i];
                if (v > bv) { bv = v; bi = i; }
            }
            #pragma unroll
            for (int o = 16; o; o >>= 1) {
                float ov = __shfl_down_sync(0xffffffffu, bv, o);
                int   oi = __shfl_down_sync(0xffffffffu, bi, o);
                if (ov > bv) { bv = ov; bi = oi; }
            }
            if ((tid & 31) == 0) { s_wv[tid >> 5] = bv; s_wi[tid >> 5] = bi; }
            __syncthreads();
            if (tid == 0) {
                float b = s_wv[0]; int x = s_wi[0];
                #pragma unroll
                for (int w = 1; w < 8; w++)
                    if (s_wv[w] > b) { b = s_wv[w]; x = s_wi[w]; }
                s_bv = b; s_bi = x;
                s_sc[x] = -FLT_MAX;        // remove winner for next iteration
            }
            __syncthreads();
            const float val = s_bv;
            const int idx = s_bi;
            if (k == 0) m0 = val;
            const float w = expf(val - m0);
            den += w;
            const float* vr = V + (size_t)idx * DMODEL;
            n0 += w * vr[tid];
            n1 += w * vr[tid + 256];
            n2 += w * vr[tid + 512];
            n3 += w * vr[tid + 768];
        }
        const float rw = g_route[row * 3 + l] / den;
        t0 += rw * n0; t1 += rw * n1; t2 += rw * n2; t3 += rw * n3;
        off += S;
        __syncthreads();
    }
    out[(size_t)row * DMODEL + tid      ] = t0;
    out[(size_t)row * DMODEL + tid + 256] = t1;
    out[(size_t)row * DMODEL + tid + 512] = t2;
    out[(size_t)row * DMODEL + tid + 768] = t3;
}

// ============================================================================
extern "C" void kernel_launch(void* const* d_in, const int* in_sizes, int n_in,
                              void* d_out, int out_size) {
    const float* q    = (const float*)d_in[0];
    const float* K0   = (const float*)d_in[1];
    const float* V0   = (const float*)d_in[2];
    const float* sal0 = (const float*)d_in[3];
    const float* K1   = (const float*)d_in[4];
    const float* V1   = (const float*)d_in[5];
    const float* sal1 = (const float*)d_in[6];
    const float* K2   = (const float*)d_in[7];
    const float* V2   = (const float*)d_in[8];
    const float* sal2 = (const float*)d_in[9];
    const float* rW1  = (const float*)d_in[10];
    const float* rb1  = (const float*)d_in[11];
    const float* rW2  = (const float*)d_in[12];
    const float* rb2  = (const float*)d_in[13];
    const float* pW1  = (const float*)d_in[14];
    const float* pb1  = (const float*)d_in[15];
    const float* pW2  = (const float*)d_in[16];
    const float* pb2  = (const float*)d_in[17];
    float* out = (float*)d_out;

    // 1) hidden = gelu(q @ rW1 + rb1)
    gemm_h_kernel<<<dim3(DMODEL / 128, BT / 128), 256>>>(q, rW1, rb1);
    // 2) route softmax + dyn_k predictor
    route_pred_kernel<<<BT, 128>>>(q, rW2, rb2, pW1, pb1, pW2, pb2);
    // 3) all score levels, one launch
    gemm_scores_kernel<<<dim3(28, BT / 128), 256>>>(q, K0, K1, K2, sal0, sal1, sal2);
    // 4) fused top-k / softmax / gather / combine
    topk_attend_kernel<<<BT, 256>>>(V0, V1, V2, out);
}

// round 3
// speedup vs baseline: 1.4314x; 1.2122x over previous
#include <cuda_runtime.h>
#include <math.h>
#include <float.h>

#define BT 2048
#define DMODEL 1024
#define S0 2048
#define S1 1024
#define S2 512
#define STOT 3584

// ---- static device scratch (no allocation allowed) ----
__device__ float g_h[BT * DMODEL];        // gelu(q@rW1+b)   8 MB
__device__ float g_scores[BT * STOT];     // all levels      29 MB
__device__ float g_route[BT * 3];
__device__ int   g_dynk[BT];

__device__ __forceinline__ float gelu_erf(float x) {
    return 0.5f * x * (1.0f + erff(x * 0.70710678118654752f));
}

// monotonic float <-> sortable uint
__device__ __forceinline__ unsigned f2key(float f) {
    unsigned b = __float_as_uint(f);
    return (b & 0x80000000u) ? ~b : (b | 0x80000000u);
}
__device__ __forceinline__ float key2f(unsigned u) {
    unsigned b = (u & 0x80000000u) ? (u ^ 0x80000000u) : ~u;
    return __uint_as_float(b);
}

// ============================================================================
// 128x128x8 SGEMM, 256 threads, 8x8 microtile (split 4+4), register prefetch.
// ============================================================================
#define BK 8
#define LDP 132   // padded smem row stride (floats)

// ---------------- NN variant: g_h = gelu(q @ rW1 + rb1) ----------------
__global__ __launch_bounds__(256, 2)
void gemm_h_kernel(const float* __restrict__ A,
                   const float* __restrict__ B,
                   const float* __restrict__ bias) {
    __shared__ float As[BK * LDP];
    __shared__ float Bs[BK * LDP];
    const int tid = threadIdx.x;
    const int tx = tid & 15, ty = tid >> 4;
    const int m0 = blockIdx.y * 128, n0 = blockIdx.x * 128;

    const int aRow = tid >> 1;
    const int aK   = (tid & 1) << 2;
    const int bK = tid >> 5;
    const int bN = (tid & 31) << 2;

    float acc[8][8] = {};
    float4 av = *(const float4*)&A[(size_t)(m0 + aRow) * DMODEL + aK];
    float4 bv = *(const float4*)&B[(size_t)bK * DMODEL + n0 + bN];

    for (int k0 = 0; k0 < DMODEL; k0 += BK) {
        As[(aK + 0) * LDP + aRow] = av.x;
        As[(aK + 1) * LDP + aRow] = av.y;
        As[(aK + 2) * LDP + aRow] = av.z;
        As[(aK + 3) * LDP + aRow] = av.w;
        *(float4*)&Bs[bK * LDP + bN] = bv;
        __syncthreads();
        if (k0 + BK < DMODEL) {
            av = *(const float4*)&A[(size_t)(m0 + aRow) * DMODEL + k0 + BK + aK];
            bv = *(const float4*)&B[(size_t)(k0 + BK + bK) * DMODEL + n0 + bN];
        }
        #pragma unroll
        for (int k = 0; k < BK; k++) {
            float4 a0 = *(const float4*)&As[k * LDP + ty * 4];
            float4 a1 = *(const float4*)&As[k * LDP + ty * 4 + 64];
            float4 b0 = *(const float4*)&Bs[k * LDP + tx * 4];
            float4 b1 = *(const float4*)&Bs[k * LDP + tx * 4 + 64];
            float a[8] = {a0.x, a0.y, a0.z, a0.w, a1.x, a1.y, a1.z, a1.w};
            float b[8] = {b0.x, b0.y, b0.z, b0.w, b1.x, b1.y, b1.z, b1.w};
            #pragma unroll
            for (int i = 0; i < 8; i++)
                #pragma unroll
                for (int j = 0; j < 8; j++)
                    acc[i][j] += a[i] * b[j];
        }
        __syncthreads();
    }
    #pragma unroll
    for (int i = 0; i < 8; i++) {
        int m = m0 + ((i < 4) ? (ty * 4 + i) : (ty * 4 + 64 + (i - 4)));
        #pragma unroll
        for (int j = 0; j < 8; j++) {
            int n = n0 + ((j < 4) ? (tx * 4 + j) : (tx * 4 + 64 + (j - 4)));
            g_h[(size_t)m * DMODEL + n] = gelu_erf(acc[i][j] + bias[n]);
        }
    }
}

// ---------------- NT variant: all three score levels in ONE launch ----------
__global__ __launch_bounds__(256, 2)
void gemm_scores_kernel(const float* __restrict__ A,
                        const float* __restrict__ K0p,
                        const float* __restrict__ K1p,
                        const float* __restrict__ K2p,
                        const float* __restrict__ sal0,
                        const float* __restrict__ sal1,
                        const float* __restrict__ sal2) {
    __shared__ float As[BK * LDP];
    __shared__ float Bs[BK * LDP];
    const int tid = threadIdx.x;
    const int tx = tid & 15, ty = tid >> 4;
    const int m0 = blockIdx.y * 128;

    const int nt = blockIdx.x;
    const float* Kb; const float* sal; int n0, col_off;
    if (nt < 16)      { Kb = K0p; sal = sal0; n0 = nt * 128;        col_off = 0; }
    else if (nt < 24) { Kb = K1p; sal = sal1; n0 = (nt - 16) * 128; col_off = S0; }
    else              { Kb = K2p; sal = sal2; n0 = (nt - 24) * 128; col_off = S0 + S1; }

    const int aRow = tid >> 1;
    const int aK   = (tid & 1) << 2;

    float acc[8][8] = {};
    float4 av = *(const float4*)&A[(size_t)(m0 + aRow) * DMODEL + aK];
    float4 bv = *(const float4*)&Kb[(size_t)(n0 + aRow) * DMODEL + aK];

    for (int k0 = 0; k0 < DMODEL; k0 += BK) {
        As[(aK + 0) * LDP + aRow] = av.x;
        As[(aK + 1) * LDP + aRow] = av.y;
        As[(aK + 2) * LDP + aRow] = av.z;
        As[(aK + 3) * LDP + aRow] = av.w;
        Bs[(aK + 0) * LDP + aRow] = bv.x;
        Bs[(aK + 1) * LDP + aRow] = bv.y;
        Bs[(aK + 2) * LDP + aRow] = bv.z;
        Bs[(aK + 3) * LDP + aRow] = bv.w;
        __syncthreads();
        if (k0 + BK < DMODEL) {
            av = *(const float4*)&A[(size_t)(m0 + aRow) * DMODEL + k0 + BK + aK];
            bv = *(const float4*)&Kb[(size_t)(n0 + aRow) * DMODEL + k0 + BK + aK];
        }
        #pragma unroll
        for (int k = 0; k < BK; k++) {
            float4 a0 = *(const float4*)&As[k * LDP + ty * 4];
            float4 a1 = *(const float4*)&As[k * LDP + ty * 4 + 64];
            float4 b0 = *(const float4*)&Bs[k * LDP + tx * 4];
            float4 b1 = *(const float4*)&Bs[k * LDP + tx * 4 + 64];
            float a[8] = {a0.x, a0.y, a0.z, a0.w, a1.x, a1.y, a1.z, a1.w};
            float b[8] = {b0.x, b0.y, b0.z, b0.w, b1.x, b1.y, b1.z, b1.w};
            #pragma unroll
            for (int i = 0; i < 8; i++)
                #pragma unroll
                for (int j = 0; j < 8; j++)
                    acc[i][j] += a[i] * b[j];
        }
        __syncthreads();
    }
    const float scale = 0.03125f;  // 1/sqrt(1024)
    #pragma unroll
    for (int i = 0; i < 8; i++) {
        int m = m0 + ((i < 4) ? (ty * 4 + i) : (ty * 4 + 64 + (i - 4)));
        #pragma unroll
        for (int j = 0; j < 8; j++) {
            int nl = (j < 4) ? (tx * 4 + j) : (tx * 4 + 64 + (j - 4));
            int n = n0 + nl;
            g_scores[(size_t)m * STOT + col_off + n] = acc[i][j] * scale + sal[n];
        }
    }
}

// ============================================================================
// Per-row router softmax (from g_h) + dyn_k predictor (from q).
// ============================================================================
__global__ void route_pred_kernel(const float* __restrict__ q,
                                  const float* __restrict__ rW2,
                                  const float* __restrict__ rb2,
                                  const float* __restrict__ pW1,
                                  const float* __restrict__ pb1,
                                  const float* __restrict__ pW2,
                                  const float* __restrict__ pb2) {
    const int row = blockIdx.x;
    const int tid = threadIdx.x;
    __shared__ float s_pred[64];

    if (tid < 32) {
        const float* h = &g_h[(size_t)row * DMODEL];
        float a0 = 0.f, a1 = 0.f, a2 = 0.f;
        for (int d = tid; d < DMODEL; d += 32) {
            float hv = h[d];
            a0 += hv * rW2[d * 3 + 0];
            a1 += hv * rW2[d * 3 + 1];
            a2 += hv * rW2[d * 3 + 2];
        }
        #pragma unroll
        for (int o = 16; o; o >>= 1) {
            a0 += __shfl_xor_sync(0xffffffffu, a0, o);
            a1 += __shfl_xor_sync(0xffffffffu, a1, o);
            a2 += __shfl_xor_sync(0xffffffffu, a2, o);
        }
        if (tid == 0) {
            a0 += rb2[0]; a1 += rb2[1]; a2 += rb2[2];
            float m = fmaxf(a0, fmaxf(a1, a2));
            float e0 = expf(a0 - m), e1 = expf(a1 - m), e2 = expf(a2 - m);
            float inv = 1.0f / (e0 + e1 + e2);
            g_route[row * 3 + 0] = e0 * inv;
            g_route[row * 3 + 1] = e1 * inv;
            g_route[row * 3 + 2] = e2 * inv;
        }
    } else if (tid < 96) {
        const int j = tid - 32;
        const float* qr = &q[(size_t)row * DMODEL];
        float acc = 0.f;
        #pragma unroll 8
        for (int d = 0; d < DMODEL; d++)
            acc += qr[d] * pW1[d * 64 + j];
        s_pred[j] = gelu_erf(acc + pb1[j]) * pW2[j];
    }
    __syncthreads();
    if (tid == 0) {
        float s = 0.f;
        for (int j = 0; j < 64; j++) s += s_pred[j];
        s += pb2[0];
        float sig = 1.0f / (1.0f + expf(-s));
        int k = (int)floorf(sig * 64.0f);
        k = max(1, min(64, k));
        g_dynk[row] = k;
    }
}

// ============================================================================
// Fused top-dyn_k (exact radix select) + softmax + V gather + route combine.
// One 256-thread block per token.
// ============================================================================
__global__ __launch_bounds__(256)
void topk_attend_kernel(const float* __restrict__ V0,
                        const float* __restrict__ V1,
                        const float* __restrict__ V2,
                        float* __restrict__ out) {
    const int row = blockIdx.x;
    const int tid = threadIdx.x;
    __shared__ unsigned s_u[S0];        // sortable keys
    __shared__ unsigned s_hist[256];
    __shared__ float    s_w[64];        // selected values, then weights
    __shared__ int      s_idx[64];
    __shared__ float    s_red[8];
    __shared__ int      s_bin, s_cgt, s_ctie;
    __shared__ float    s_m, s_den;

    const int dynk = g_dynk[row];
    const float* Vp[3] = {V0, V1, V2};
    const int Ss[3] = {S0, S1, S2};

    float4 tot = make_float4(0.f, 0.f, 0.f, 0.f);
    int off = 0;
    for (int l = 0; l < 3; l++) {
        const int S = Ss[l];
        const float* V = Vp[l];

        // ---- load scores, convert to sortable keys, block max ----
        float lmax = -FLT_MAX;
        for (int i = tid; i < S; i += 256) {
            float v = g_scores[(size_t)row * STOT + off + i];
            lmax = fmaxf(lmax, v);
            s_u[i] = f2key(v);
        }
        #pragma unroll
        for (int o = 16; o; o >>= 1)
            lmax = fmaxf(lmax, __shfl_xor_sync(0xffffffffu, lmax, o));
        if ((tid & 31) == 0) s_red[tid >> 5] = lmax;
        __syncthreads();
        if (tid == 0) {
            float m = s_red[0];
            #pragma unroll
            for (int w = 1; w < 8; w++) m = fmaxf(m, s_red[w]);
            s_m = m;
        }

        // ---- radix select: exact dynk-th largest key ----
        unsigned fixedk = 0;
        int kr = dynk;
        for (int p = 3; p >= 0; p--) {
            __syncthreads();
            s_hist[tid] = 0;
            __syncthreads();
            const int sh = p << 3;
            for (int i = tid; i < S; i += 256) {
                unsigned u = s_u[i];
                bool cand = (p == 3) || (((u ^ fixedk) >> (sh + 8)) == 0);
                if (cand) atomicAdd(&s_hist[(u >> sh) & 0xFFu], 1u);
            }
            __syncthreads();
            // suffix sum: s_hist[b] = # candidates with byte >= b
            #pragma unroll
            for (int o = 1; o < 256; o <<= 1) {
                unsigned v = (tid + o < 256) ? s_hist[tid + o] : 0u;
                __syncthreads();
                s_hist[tid] += v;
                __syncthreads();
            }
            if (s_hist[tid] >= (unsigned)kr &&
                (tid == 255 || s_hist[tid + 1] < (unsigned)kr))
                s_bin = tid;
            __syncthreads();
            const int b = s_bin;
            if (b < 255) kr -= (int)s_hist[b + 1];
            fixedk |= (unsigned)b << sh;
        }
        const unsigned T = fixedk;   // exact dynk-th largest key; kr = #ties to take

        // ---- compaction: u > T all selected; kr copies of u == T ----
        if (tid == 0) { s_cgt = 0; s_ctie = 0; }
        __syncthreads();
        const int tie_base = dynk - kr;
        for (int i = tid; i < S; i += 256) {
            unsigned u = s_u[i];
            if (u > T) {
                int pos = atomicAdd(&s_cgt, 1);
                s_idx[pos] = i; s_w[pos] = key2f(u);
            } else if (u == T) {
                int p = atomicAdd(&s_ctie, 1);
                if (p < kr) { s_idx[tie_base + p] = i; s_w[tie_base + p] = key2f(u); }
            }
        }
        __syncthreads();

        // ---- weights + denominator ----
        const float m = s_m;
        if (tid < 64)
            s_w[tid] = (tid < dynk) ? expf(s_w[tid] - m) : 0.f;
        __syncthreads();
        if (tid < 32) {
            float d = s_w[tid] + s_w[tid + 32];
            #pragma unroll
            for (int o = 16; o; o >>= 1)
                d += __shfl_xor_sync(0xffffffffu, d, o);
            if (tid == 0) s_den = d;
        }
        __syncthreads();

        // ---- gather: each thread owns 4 contiguous cols (float4) ----
        float4 acc = make_float4(0.f, 0.f, 0.f, 0.f);
        const float4* V4 = (const float4*)V;
        #pragma unroll 4
        for (int k = 0; k < dynk; k++) {
            const float w = s_w[k];
            const float4 v = V4[(size_t)s_idx[k] * 256 + tid];
            acc.x += w * v.x; acc.y += w * v.y;
            acc.z += w * v.z; acc.w += w * v.w;
        }
        const float rw = g_route[row * 3 + l] / s_den;
        tot.x += rw * acc.x; tot.y += rw * acc.y;
        tot.z += rw * acc.z; tot.w += rw * acc.w;
        off += S;
        __syncthreads();   // protect s_u reuse next level
    }
    ((float4*)out)[(size_t)row * 256 + tid] = tot;
}

// ============================================================================
extern "C" void kernel_launch(void* const* d_in, const int* in_sizes, int n_in,
                              void* d_out, int out_size) {
    const float* q    = (const float*)d_in[0];
    const float* K0   = (const float*)d_in[1];
    const float* V0   = (const float*)d_in[2];
    const float* sal0 = (const float*)d_in[3];
    const float* K1   = (const float*)d_in[4];
    const float* V1   = (const float*)d_in[5];
    const float* sal1 = (const float*)d_in[6];
    const float* K2   = (const float*)d_in[7];
    const float* V2   = (const float*)d_in[8];
    const float* sal2 = (const float*)d_in[9];
    const float* rW1  = (const float*)d_in[10];
    const float* rb1  = (const float*)d_in[11];
    const float* rW2  = (const float*)d_in[12];
    const float* rb2  = (const float*)d_in[13];
    const float* pW1  = (const float*)d_in[14];
    const float* pb1  = (const float*)d_in[15];
    const float* pW2  = (const float*)d_in[16];
    const float* pb2  = (const float*)d_in[17];
    float* out = (float*)d_out;

    gemm_h_kernel<<<dim3(DMODEL / 128, BT / 128), 256>>>(q, rW1, rb1);
    route_pred_kernel<<<BT, 128>>>(q, rW2, rb2, pW1, pb1, pW2, pb2);
    gemm_scores_kernel<<<dim3(28, BT / 128), 256>>>(q, K0, K1, K2, sal0, sal1, sal2);
    topk_attend_kernel<<<BT, 256>>>(V0, V1, V2, out);
}